// round 14
// baseline (speedup 1.0000x reference)
#include <cuda_runtime.h>
#include <cuda_fp16.h>
#include <stdint.h>

#define BT   2048
#define TPH  32
#define EDIM 128
#define HDIM 256
#define GDIM 1024
#define VOC  256

#define NCTA 128
#define MT   128
#define NTP  128

// ---------------- smem map (bytes) ----------------
#define W_ROW_B   528
#define W_PLANE_B (128 * W_ROW_B)        // 67584
#define SM_W      0
#define FCW_PL_B  (32 * W_ROW_B)         // 16896
#define SM_FCW    (2 * W_PLANE_B)        // 135168
#define SM_STG    (SM_FCW + 2 * FCW_PL_B) // 168960
#define A_PL_B    10240                  // 128 rows x 80 B
#define A_CH_B    20480
#define SM_BIAS   (SM_STG + 3 * A_CH_B)  // 230400 (32 f32)
#define SM_TOK    (SM_BIAS + 128)        // 230528 (128 i32: SLEN in enc / STOK in dec)
#define SM_TOTAL  (SM_TOK + 512)         // 231040  (< 232448 max)

// overlays inside stage region (valid when stages idle)
#define SHI_OFF   SM_STG                 // 128*34 halfs
#define SLO_OFF   (SM_STG + 8704)
#define SSC_OFF   SM_STG                 // 128*33 f32
#define PV_OFF    SM_STG                 // 8*128 f32
#define PI_OFF    (SM_STG + 4096)        // 8*128 i32

// ---------------- device scratch ----------------
__device__ float   g_projP[2][VOC * GDIM];
__device__ __half  g_Ws[2][2][GDIM * HDIM];
__device__ __half  g_fcWs[2][VOC * HDIM];
__device__ __half  g_hs[2][2][BT * HDIM];
__device__ __half  g_eL[2][BT * HDIM];
__device__ float   g_pval[8][BT];
__device__ int     g_pidx[8][BT];
__device__ unsigned          g_bar_cnt = 0;
__device__ volatile unsigned g_bar_sense = 0;

// ---------------- fast pointwise ----------------
__device__ __forceinline__ float fast_sigmoid(float x) {
    return __fdividef(1.f, 1.f + __expf(-x));
}
__device__ __forceinline__ float fast_tanh(float x) {
    return 1.f - __fdividef(2.f, __expf(2.f * x) + 1.f);
}

// ---------------- PTX helpers ----------------
__device__ __forceinline__ uint32_t smem_u32(const void* p) {
    uint32_t a;
    asm("{ .reg .u64 t; cvta.to.shared.u64 t, %1; cvt.u32.u64 %0, t; }" : "=r"(a) : "l"(p));
    return a;
}
__device__ __forceinline__ void cpa16(uint32_t saddr, const void* g) {
    asm volatile("cp.async.cg.shared.global [%0], [%1], 16;" :: "r"(saddr), "l"(g));
}
__device__ __forceinline__ void cpa_commit() {
    asm volatile("cp.async.commit_group;" ::: "memory");
}
template <int N>
__device__ __forceinline__ void cpa_wait() {
    asm volatile("cp.async.wait_group %0;" :: "n"(N) : "memory");
}
__device__ __forceinline__ void ldsm4(uint32_t* r, uint32_t addr) {
    asm volatile("ldmatrix.sync.aligned.m8n8.x4.shared.b16 {%0,%1,%2,%3}, [%4];"
        : "=r"(r[0]), "=r"(r[1]), "=r"(r[2]), "=r"(r[3]) : "r"(addr));
}
__device__ __forceinline__ void ldsm2(uint32_t* r, uint32_t addr) {
    asm volatile("ldmatrix.sync.aligned.m8n8.x2.shared.b16 {%0,%1}, [%2];"
        : "=r"(r[0]), "=r"(r[1]) : "r"(addr));
}
__device__ __forceinline__ void mma16816(float* c, const uint32_t* a,
                                         uint32_t b0, uint32_t b1) {
    asm volatile("mma.sync.aligned.m16n8k16.row.col.f32.f16.f16.f32 "
        "{%0,%1,%2,%3}, {%4,%5,%6,%7}, {%8,%9}, {%0,%1,%2,%3};"
        : "+f"(c[0]), "+f"(c[1]), "+f"(c[2]), "+f"(c[3])
        : "r"(a[0]), "r"(a[1]), "r"(a[2]), "r"(a[3]), "r"(b0), "r"(b1));
}

// ---------------- grid barrier ----------------
__device__ __forceinline__ void grid_sync(unsigned& sense) {
    sense ^= 1u;
    __syncthreads();
    if (threadIdx.x == 0) {
        __threadfence();
        if (atomicAdd(&g_bar_cnt, 1u) == NCTA - 1) {
            g_bar_cnt = 0;
            __threadfence();
            g_bar_sense = sense;
        } else {
            while (g_bar_sense != sense) __nanosleep(32);
        }
        __threadfence();
    }
    __syncthreads();
}

// ---------------- merged prep (one launch) ----------------
// blocks [0,2048): split Whh   [2048,2304): split fcW
// blocks [2304,4352): init h   [4352,6400): proj tables
__global__ void prep_kernel(const float* __restrict__ Wenc,
                            const float* __restrict__ Wdec,
                            const float* __restrict__ fcW,
                            const float* __restrict__ emb,
                            const float* __restrict__ eWih,
                            const float* __restrict__ eB1,
                            const float* __restrict__ eB2,
                            const float* __restrict__ dWih,
                            const float* __restrict__ dB1,
                            const float* __restrict__ dB2)
{
    __shared__ float es[EDIM];
    const int bid = blockIdx.x;
    const int tid = threadIdx.x;
    if (bid < 2048) {
        int gidx = bid * 256 + tid;
        int which = gidx >= GDIM * HDIM;
        int idx = gidx - which * (GDIM * HDIM);
        const float* W = which ? Wdec : Wenc;
        int np = idx >> 8, k = idx & 255;
        int j = np >> 2, g = np & 3;
        float w = W[(size_t)(g * HDIM + j) * HDIM + k];
        __half hi = __float2half_rn(w);
        __half lo = __float2half_rn(w - __half2float(hi));
        g_Ws[which][0][idx] = hi;
        g_Ws[which][1][idx] = lo;
    } else if (bid < 2304) {
        int idx = (bid - 2048) * 256 + tid;
        float w = fcW[idx];
        __half hi = __float2half_rn(w);
        __half lo = __float2half_rn(w - __half2float(hi));
        g_fcWs[0][idx] = hi;
        g_fcWs[1][idx] = lo;
    } else if (bid < 4352) {
        int i = (bid - 2304) * 256 + tid;
        __half z = __float2half_rn(0.f);
        g_hs[0][0][i] = z; g_hs[0][1][i] = z;
    } else {
        int pb = bid - 4352;
        int v = pb >> 3, sub = pb & 7;
        int which = sub >> 2, ny = sub & 3;
        const float* W  = which ? dWih : eWih;
        const float* b1 = which ? dB1 : eB1;
        const float* b2 = which ? dB2 : eB2;
        if (tid < EDIM) es[tid] = emb[v * EDIM + tid];
        __syncthreads();
        int n = ny * 256 + tid;
        const float4* wr = (const float4*)(W + (size_t)n * EDIM);
        float a0 = 0.f, a1 = 0.f, a2 = 0.f, a3 = 0.f;
#pragma unroll
        for (int k4 = 0; k4 < EDIM / 16; k4++) {
            float4 w0 = wr[k4 * 4 + 0];
            float4 w1 = wr[k4 * 4 + 1];
            float4 w2 = wr[k4 * 4 + 2];
            float4 w3 = wr[k4 * 4 + 3];
            const float* e = es + k4 * 16;
            a0 += e[0] * w0.x + e[1] * w0.y + e[2] * w0.z + e[3] * w0.w;
            a1 += e[4] * w1.x + e[5] * w1.y + e[6] * w1.z + e[7] * w1.w;
            a2 += e[8] * w2.x + e[9] * w2.y + e[10] * w2.z + e[11] * w2.w;
            a3 += e[12] * w3.x + e[13] * w3.y + e[14] * w3.z + e[15] * w3.w;
        }
        int np = (n & 255) * 4 + (n >> 8);
        g_projP[which][(size_t)v * GDIM + np] = (a0 + a1) + (a2 + a3) + b1[n] + b2[n];
    }
}

// ---------------- A-chunk loader (h splits, k=32) ----------------
__device__ __forceinline__ void load_chunk(uint32_t dst, const __half* __restrict__ A0,
                                           const __half* __restrict__ A1,
                                           int m0, int kb, int tid)
{
    const int row = tid >> 1;
    const int half = tid & 1;
    const uint32_t d0 = dst + (uint32_t)(row * 80 + half * 32);
    const size_t s0 = (size_t)(m0 + row) * HDIM + kb * 32 + half * 16;
    cpa16(d0,               A0 + s0);
    cpa16(d0 + 16,          A0 + s0 + 8);
    cpa16(d0 + A_PL_B,      A1 + s0);
    cpa16(d0 + A_PL_B + 16, A1 + s0 + 8);
}

// ---------------- persistent kernel ----------------
__global__ void __launch_bounds__(256, 1)
persist_kernel(const int* __restrict__ phon, const int* __restrict__ lens,
               const float* __restrict__ fcb, const int* __restrict__ sos,
               float* __restrict__ out)
{
    extern __shared__ char smem[];
    const uint32_t sb = smem_u32(smem);

    const int tid  = threadIdx.x;
    const int lane = tid & 31;
    const int wid  = tid >> 5;
    const int wm = wid & 1, wn = wid >> 1;
    const int bm = blockIdx.x >> 3, bn = blockIdx.x & 7;
    const int m0 = bm * MT;
    const int n0 = bn * NTP;
    const int j0g = bn * 32;

    unsigned sense = 0;
    const int sos0 = sos[0];

    if (tid < 32) ((float*)(smem + SM_BIAS))[tid] = fcb[bn * 32 + tid];
    if (tid < 128) ((int*)(smem + SM_TOK))[tid] = lens[m0 + tid];  // SLEN (enc phase)

    const int aRow = wm * 64 + (lane & 15);
    const int aCol = (lane >> 4) * 8;
    const int bRow = wn * 32 + ((lane & 16) >> 1) + (lane & 7);
    const int bColH = ((lane >> 3) & 1) * 8;
    const int myRow = wm * 64 + (lane >> 2) + (lane & 1) * 8;
    const int myUlB = wn * 8 + ((lane & 2) >> 1);
    const bool odd = (lane & 1);

    // resident W loader; also stages the fcW slice when entering decoder
    auto load_W = [&](int mode) {
        for (int f = tid; f < 8192; f += 256) {
            int p = f >> 12, rem = f & 4095;
            int row = rem >> 5, seg = rem & 31;
            cpa16(sb + SM_W + p * W_PLANE_B + row * W_ROW_B + seg * 16,
                  g_Ws[mode][p] + (size_t)(n0 + row) * HDIM + seg * 8);
        }
        if (mode) {
            for (int f = tid; f < 2048; f += 256) {
                int p = f >> 10, rem = f & 1023;
                int row = rem >> 5, seg = rem & 31;
                cpa16(sb + SM_FCW + p * FCW_PL_B + row * W_ROW_B + seg * 16,
                      g_fcWs[p] + (size_t)(bn * 32 + row) * HDIM + seg * 8);
            }
        }
        cpa_commit();
        cpa_wait<0>();
        __syncthreads();
    };
    load_W(0);

    float cpre[4][4];
#pragma unroll
    for (int i = 0; i < 4; i++)
#pragma unroll
        for (int j = 0; j < 4; j++) cpre[i][j] = 0.f;

    for (int t = 0; t < 2 * TPH; t++) {
        const int mode = (t >= TPH);
        if (t == TPH) {
            load_W(1);
#pragma unroll
            for (int i = 0; i < 4; i++)
#pragma unroll
                for (int j = 0; j < 4; j++) cpre[i][j] = 0.f;
        }
        const int inPar = t & 1, outPar = inPar ^ 1;
        const __half* A0 = (t == TPH) ? g_eL[0] : g_hs[inPar][0];
        const __half* A1 = (t == TPH) ? g_eL[1] : g_hs[inPar][1];

        // ---- token resolution ----
        int tokr[4];
        if (!mode) {
#pragma unroll
            for (int mt = 0; mt < 4; mt++)
                tokr[mt] = phon[(m0 + myRow + mt * 16) * TPH + t];
        } else if (t == TPH) {
#pragma unroll
            for (int mt = 0; mt < 4; mt++) tokr[mt] = sos0;
        } else {
            // reduce fc partials (8 slices) cooperatively
            float* PV = (float*)(smem + PV_OFF);
            int*   PI = (int*)(smem + PI_OFF);
#pragma unroll
            for (int i = 0; i < 4; i++) {
                int f = tid + i * 256;
                int bnp = f >> 7, lm = f & 127;
                PV[f] = g_pval[bnp][m0 + lm];
                PI[f] = g_pidx[bnp][m0 + lm];
            }
            __syncthreads();
            int* STOK = (int*)(smem + SM_TOK);
            if (tid < 128) {
                float bv = PV[tid];
                int   bi = PI[tid];
#pragma unroll
                for (int b = 1; b < 8; b++) {
                    float ov = PV[b * 128 + tid];
                    int   oi = PI[b * 128 + tid];
                    if (ov > bv || (ov == bv && oi < bi)) { bv = ov; bi = oi; }
                }
                STOK[tid] = bi;
            }
            __syncthreads();
#pragma unroll
            for (int mt = 0; mt < 4; mt++)
                tokr[mt] = STOK[myRow + mt * 16];
        }

        float acc[4][4][4];
#pragma unroll
        for (int i = 0; i < 4; i++)
#pragma unroll
            for (int j = 0; j < 4; j++)
#pragma unroll
                for (int q = 0; q < 4; q++) acc[i][j][q] = 0.f;

        load_chunk(sb + SM_STG, A0, A1, m0, 0, tid); cpa_commit();
        load_chunk(sb + SM_STG + A_CH_B, A0, A1, m0, 1, tid); cpa_commit();

        for (int kb = 0; kb < 8; kb++) {
            if (kb < 7) cpa_wait<1>(); else cpa_wait<0>();
            __syncthreads();
            if (kb < 6) {
                load_chunk(sb + SM_STG + ((kb + 2) % 3) * A_CH_B, A0, A1, m0, kb + 2, tid);
                cpa_commit();
            }
            const uint32_t bA = sb + SM_STG + (kb % 3) * A_CH_B;
#pragma unroll
            for (int k16 = 0; k16 < 2; k16++) {
                const uint32_t aOff = (uint32_t)(k16 * 16 + aCol) * 2;
                const uint32_t kW = (uint32_t)(kb * 32 + k16 * 16 + bColH) * 2;
                uint32_t ah[4][4], al[4][4], bh[2][4], bl[2][4];
#pragma unroll
                for (int mt = 0; mt < 4; mt++) {
                    ldsm4(ah[mt], bA + (uint32_t)(aRow + mt * 16) * 80 + aOff);
                    ldsm4(al[mt], bA + A_PL_B + (uint32_t)(aRow + mt * 16) * 80 + aOff);
                }
#pragma unroll
                for (int bg = 0; bg < 2; bg++) {
                    ldsm4(bh[bg], sb + SM_W + (uint32_t)(bRow + bg * 16) * W_ROW_B + kW);
                    ldsm4(bl[bg], sb + SM_W + W_PLANE_B
                                   + (uint32_t)(bRow + bg * 16) * W_ROW_B + kW);
                }
#pragma unroll
                for (int mt = 0; mt < 4; mt++)
#pragma unroll
                    for (int nt = 0; nt < 4; nt++) {
                        const int g = nt >> 1, s = (nt & 1) * 2;
                        mma16816(acc[mt][nt], ah[mt], bh[g][s], bh[g][s + 1]);
                    }
#pragma unroll
                for (int mt = 0; mt < 4; mt++)
#pragma unroll
                    for (int nt = 0; nt < 4; nt++) {
                        const int g = nt >> 1, s = (nt & 1) * 2;
                        mma16816(acc[mt][nt], ah[mt], bl[g][s], bl[g][s + 1]);
                    }
#pragma unroll
                for (int mt = 0; mt < 4; mt++)
#pragma unroll
                    for (int nt = 0; nt < 4; nt++) {
                        const int g = nt >> 1, s = (nt & 1) * 2;
                        mma16816(acc[mt][nt], al[mt], bh[g][s], bh[g][s + 1]);
                    }
            }
            __syncthreads();
        }

        // ---- epilogue ----
        __half* SHI = (__half*)(smem + SHI_OFF);
        __half* SLO = (__half*)(smem + SLO_OFF);
        const float* projT = g_projP[mode];
#pragma unroll
        for (int mt = 0; mt < 4; mt++) {
#pragma unroll
            for (int nt = 0; nt < 4; nt++) {
                const int ul = myUlB + nt * 2;
                const float4 p = *(const float4*)&projT[(size_t)tokr[mt] * GDIM
                                                        + n0 + ul * 4];
                float c0 = acc[mt][nt][0], c1 = acc[mt][nt][1];
                float c2 = acc[mt][nt][2], c3 = acc[mt][nt][3];
                float sA = odd ? c0 : c2;
                float sB = odd ? c1 : c3;
                float rA = __shfl_xor_sync(0xffffffffu, sA, 1);
                float rB = __shfl_xor_sync(0xffffffffu, sB, 1);
                float gi = odd ? rA : c0;
                float gf = odd ? rB : c1;
                float gg = odd ? c2 : rA;
                float go = odd ? c3 : rB;
                float iv = fast_sigmoid(gi + p.x);
                float fv = fast_sigmoid(gf + p.y);
                float gv = fast_tanh(gg + p.z);
                float ov = fast_sigmoid(go + p.w);
                float cn = fv * cpre[mt][nt] + iv * gv;
                cpre[mt][nt] = cn;
                float hv = ov * fast_tanh(cn);
                __half hi = __float2half_rn(hv);
                __half lo = __float2half_rn(hv - __half2float(hi));
                const int lr = myRow + mt * 16;
                SHI[lr * 34 + ul] = hi;
                SLO[lr * 34 + ul] = lo;
            }
        }
        __syncthreads();

        __half* oHi = g_hs[outPar][0];
        __half* oLo = g_hs[outPar][1];
        const int* SLEN = (const int*)(smem + SM_TOK);
#pragma unroll
        for (int i = 0; i < 16; i++) {
            int f = tid + i * 256;
            int lm = f >> 5, jl = f & 31;
            size_t gidx = (size_t)(m0 + lm) * HDIM + j0g + jl;
            __half hi = SHI[lm * 34 + jl];
            __half lo = SLO[lm * 34 + jl];
            oHi[gidx] = hi;
            oLo[gidx] = lo;
            if (!mode && t == SLEN[lm] - 1) {
                g_eL[0][gidx] = hi;
                g_eL[1][gidx] = lo;
            }
        }
        grid_sync(sense);

        // ================= fc: V-sliced, resident fcW =================
        if (mode) {
            const __half* hH = g_hs[outPar][0];
            const __half* hL = g_hs[outPar][1];
            const int wm2 = wid & 1, wn2 = wid >> 1;
            const int aRowF = wm2 * 64 + (lane & 15);
            const int fbRow = wn2 * 8 + (lane & 7);
            const int fbColH = ((lane >> 3) & 1) * 8;

            float accF[4][4];
#pragma unroll
            for (int i = 0; i < 4; i++)
#pragma unroll
                for (int j = 0; j < 4; j++) accF[i][j] = 0.f;

            load_chunk(sb + SM_STG, hH, hL, m0, 0, tid); cpa_commit();
            load_chunk(sb + SM_STG + A_CH_B, hH, hL, m0, 1, tid); cpa_commit();

            for (int kb = 0; kb < 8; kb++) {
                if (kb < 7) cpa_wait<1>(); else cpa_wait<0>();
                __syncthreads();
                if (kb < 6) {
                    load_chunk(sb + SM_STG + ((kb + 2) % 3) * A_CH_B, hH, hL, m0, kb + 2, tid);
                    cpa_commit();
                }
                const uint32_t bA = sb + SM_STG + (kb % 3) * A_CH_B;
#pragma unroll
                for (int k16 = 0; k16 < 2; k16++) {
                    const uint32_t aOff = (uint32_t)(k16 * 16 + aCol) * 2;
                    const uint32_t kF = (uint32_t)(kb * 32 + k16 * 16 + fbColH) * 2;
                    uint32_t fa_h[4][4], fa_l[4][4], fb_h[2], fb_l[2];
#pragma unroll
                    for (int mt = 0; mt < 4; mt++) {
                        ldsm4(fa_h[mt], bA + (uint32_t)(aRowF + mt * 16) * 80 + aOff);
                        ldsm4(fa_l[mt], bA + A_PL_B + (uint32_t)(aRowF + mt * 16) * 80 + aOff);
                    }
                    ldsm2(fb_h, sb + SM_FCW + (uint32_t)fbRow * W_ROW_B + kF);
                    ldsm2(fb_l, sb + SM_FCW + FCW_PL_B + (uint32_t)fbRow * W_ROW_B + kF);
#pragma unroll
                    for (int mt = 0; mt < 4; mt++) {
                        mma16816(accF[mt], fa_h[mt], fb_h[0], fb_h[1]);
                        mma16816(accF[mt], fa_h[mt], fb_l[0], fb_l[1]);
                        mma16816(accF[mt], fa_l[mt], fb_h[0], fb_h[1]);
                    }
                }
                __syncthreads();
            }

            // stage scores: rows 128, cols 8 per warp-n-group (total 32)
            float* SSC = (float*)(smem + SSC_OFF);
#pragma unroll
            for (int mt = 0; mt < 4; mt++) {
                int r = wm2 * 64 + mt * 16 + (lane >> 2);
                int c = wn2 * 8 + (lane & 3) * 2;
                SSC[r * 33 + c]       = accF[mt][0];
                SSC[r * 33 + c + 1]   = accF[mt][1];
                SSC[(r + 8) * 33 + c]     = accF[mt][2];
                SSC[(r + 8) * 33 + c + 1] = accF[mt][3];
            }
            __syncthreads();

            // bias + out + per-slice argmax; each warp handles 16 rows
            const float* SBIA = (const float*)(smem + SM_BIAS);
            const float myb = SBIA[lane];
#pragma unroll
            for (int rr = 0; rr < 16; rr++) {
                const int r = wid * 16 + rr;
                const int m = m0 + r;
                float s = SSC[r * 33 + lane] + myb;
                out[(size_t)m * (TPH * VOC) + (size_t)(t - TPH) * VOC + bn * 32 + lane] = s;
                float bv = s;
                int   bi = lane;
#pragma unroll
                for (int off = 16; off > 0; off >>= 1) {
                    float ov = __shfl_xor_sync(0xffffffffu, bv, off);
                    int   oi = __shfl_xor_sync(0xffffffffu, bi, off);
                    if (ov > bv || (ov == bv && oi < bi)) { bv = ov; bi = oi; }
                }
                if (lane == 0) {
                    g_pval[bn][m] = bv;
                    g_pidx[bn][m] = bn * 32 + bi;
                }
            }
            grid_sync(sense);
        }
    }
}

// ---------------- launch ----------------
extern "C" void kernel_launch(void* const* d_in, const int* in_sizes, int n_in,
                              void* d_out, int out_size)
{
    const int*   phon   = (const int*)  d_in[0];
    const int*   plen   = (const int*)  d_in[1];
    const float* emb    = (const float*)d_in[2];
    const float* encWih = (const float*)d_in[3];
    const float* encWhh = (const float*)d_in[4];
    const float* encBih = (const float*)d_in[5];
    const float* encBhh = (const float*)d_in[6];
    const float* decWih = (const float*)d_in[7];
    const float* decWhh = (const float*)d_in[8];
    const float* decBih = (const float*)d_in[9];
    const float* decBhh = (const float*)d_in[10];
    const float* fcW    = (const float*)d_in[11];
    const float* fcb    = (const float*)d_in[12];
    const int*   sos    = (const int*)  d_in[13];
    float* out = (float*)d_out;

    cudaFuncSetAttribute(persist_kernel,
                         cudaFuncAttributeMaxDynamicSharedMemorySize, SM_TOTAL);

    prep_kernel<<<6400, 256>>>(encWhh, decWhh, fcW, emb,
                               encWih, encBih, encBhh,
                               decWih, decBih, decBhh);

    persist_kernel<<<NCTA, 256, SM_TOTAL>>>(phon, plen, fcb, sos, out);
}

// round 15
// speedup vs baseline: 1.0033x; 1.0033x over previous
#include <cuda_runtime.h>
#include <cuda_fp16.h>
#include <stdint.h>

#define BT   2048
#define TPH  32
#define EDIM 128
#define HDIM 256
#define GDIM 1024
#define VOC  256

#define NCTA 128
#define MT   128
#define NTP  128

// ---------------- smem map (bytes) ----------------
#define W_ROW_B   528
#define W_PLANE_B (128 * W_ROW_B)        // 67584
#define SM_W      0
#define FCW_PL_B  (32 * W_ROW_B)         // 16896
#define SM_FCW    (2 * W_PLANE_B)        // 135168
#define SM_STG    (SM_FCW + 2 * FCW_PL_B) // 168960
#define A_PL_B    10240                  // 128 rows x 80 B
#define A_CH_B    20480
#define SM_BIAS   (SM_STG + 3 * A_CH_B)  // 230400 (32 f32)
#define SM_TOK    (SM_BIAS + 128)        // 230528 (128 i32: SLEN in enc / STOK in dec)
#define SM_TOTAL  (SM_TOK + 512)         // 231040  (< 232448 max)

// overlays inside stage region (valid when stages idle)
#define SHI_OFF   SM_STG                 // 128*34 halfs
#define SLO_OFF   (SM_STG + 8704)
#define SSC_OFF   SM_STG                 // 128*33 f32
#define PV_OFF    SM_STG                 // 8*128 f32
#define PI_OFF    (SM_STG + 4096)        // 8*128 i32

// ---------------- device scratch ----------------
__device__ float   g_projP[2][VOC * GDIM];
__device__ __half  g_Ws[2][2][GDIM * HDIM];
__device__ __half  g_fcWs[2][VOC * HDIM];
__device__ __half  g_hs[2][2][BT * HDIM];
__device__ __half  g_eL[2][BT * HDIM];
__device__ float   g_pval[8][BT];
__device__ int     g_pidx[8][BT];
__device__ unsigned          g_bar_cnt = 0;
__device__ volatile unsigned g_bar_sense = 0;

// ---------------- fast pointwise ----------------
__device__ __forceinline__ float fast_sigmoid(float x) {
    return __fdividef(1.f, 1.f + __expf(-x));
}
__device__ __forceinline__ float fast_tanh(float x) {
    return 1.f - __fdividef(2.f, __expf(2.f * x) + 1.f);
}

// ---------------- PTX helpers ----------------
__device__ __forceinline__ uint32_t smem_u32(const void* p) {
    uint32_t a;
    asm("{ .reg .u64 t; cvta.to.shared.u64 t, %1; cvt.u32.u64 %0, t; }" : "=r"(a) : "l"(p));
    return a;
}
__device__ __forceinline__ void cpa16(uint32_t saddr, const void* g) {
    asm volatile("cp.async.cg.shared.global [%0], [%1], 16;" :: "r"(saddr), "l"(g));
}
__device__ __forceinline__ void cpa_commit() {
    asm volatile("cp.async.commit_group;" ::: "memory");
}
template <int N>
__device__ __forceinline__ void cpa_wait() {
    asm volatile("cp.async.wait_group %0;" :: "n"(N) : "memory");
}
__device__ __forceinline__ void ldsm4(uint32_t* r, uint32_t addr) {
    asm volatile("ldmatrix.sync.aligned.m8n8.x4.shared.b16 {%0,%1,%2,%3}, [%4];"
        : "=r"(r[0]), "=r"(r[1]), "=r"(r[2]), "=r"(r[3]) : "r"(addr));
}
__device__ __forceinline__ void ldsm2(uint32_t* r, uint32_t addr) {
    asm volatile("ldmatrix.sync.aligned.m8n8.x2.shared.b16 {%0,%1}, [%2];"
        : "=r"(r[0]), "=r"(r[1]) : "r"(addr));
}
__device__ __forceinline__ void mma16816(float* c, const uint32_t* a,
                                         uint32_t b0, uint32_t b1) {
    asm volatile("mma.sync.aligned.m16n8k16.row.col.f32.f16.f16.f32 "
        "{%0,%1,%2,%3}, {%4,%5,%6,%7}, {%8,%9}, {%0,%1,%2,%3};"
        : "+f"(c[0]), "+f"(c[1]), "+f"(c[2]), "+f"(c[3])
        : "r"(a[0]), "r"(a[1]), "r"(a[2]), "r"(a[3]), "r"(b0), "r"(b1));
}

// ---------------- grid barrier ----------------
__device__ __forceinline__ void grid_sync(unsigned& sense) {
    sense ^= 1u;
    __syncthreads();
    if (threadIdx.x == 0) {
        __threadfence();
        if (atomicAdd(&g_bar_cnt, 1u) == NCTA - 1) {
            g_bar_cnt = 0;
            __threadfence();
            g_bar_sense = sense;
        } else {
            while (g_bar_sense != sense) __nanosleep(32);
        }
        __threadfence();
    }
    __syncthreads();
}

// ---------------- merged prep (one launch) ----------------
// blocks [0,2048): split Whh   [2048,2304): split fcW
// blocks [2304,4352): init h   [4352,6400): proj tables
__global__ void prep_kernel(const float* __restrict__ Wenc,
                            const float* __restrict__ Wdec,
                            const float* __restrict__ fcW,
                            const float* __restrict__ emb,
                            const float* __restrict__ eWih,
                            const float* __restrict__ eB1,
                            const float* __restrict__ eB2,
                            const float* __restrict__ dWih,
                            const float* __restrict__ dB1,
                            const float* __restrict__ dB2)
{
    __shared__ float es[EDIM];
    const int bid = blockIdx.x;
    const int tid = threadIdx.x;
    if (bid < 2048) {
        int gidx = bid * 256 + tid;
        int which = gidx >= GDIM * HDIM;
        int idx = gidx - which * (GDIM * HDIM);
        const float* W = which ? Wdec : Wenc;
        int np = idx >> 8, k = idx & 255;
        int j = np >> 2, g = np & 3;
        float w = W[(size_t)(g * HDIM + j) * HDIM + k];
        __half hi = __float2half_rn(w);
        __half lo = __float2half_rn(w - __half2float(hi));
        g_Ws[which][0][idx] = hi;
        g_Ws[which][1][idx] = lo;
    } else if (bid < 2304) {
        int idx = (bid - 2048) * 256 + tid;
        float w = fcW[idx];
        __half hi = __float2half_rn(w);
        __half lo = __float2half_rn(w - __half2float(hi));
        g_fcWs[0][idx] = hi;
        g_fcWs[1][idx] = lo;
    } else if (bid < 4352) {
        int i = (bid - 2304) * 256 + tid;
        __half z = __float2half_rn(0.f);
        g_hs[0][0][i] = z; g_hs[0][1][i] = z;
    } else {
        int pb = bid - 4352;
        int v = pb >> 3, sub = pb & 7;
        int which = sub >> 2, ny = sub & 3;
        const float* W  = which ? dWih : eWih;
        const float* b1 = which ? dB1 : eB1;
        const float* b2 = which ? dB2 : eB2;
        if (tid < EDIM) es[tid] = emb[v * EDIM + tid];
        __syncthreads();
        int n = ny * 256 + tid;
        const float4* wr = (const float4*)(W + (size_t)n * EDIM);
        float a0 = 0.f, a1 = 0.f, a2 = 0.f, a3 = 0.f;
#pragma unroll
        for (int k4 = 0; k4 < EDIM / 16; k4++) {
            float4 w0 = wr[k4 * 4 + 0];
            float4 w1 = wr[k4 * 4 + 1];
            float4 w2 = wr[k4 * 4 + 2];
            float4 w3 = wr[k4 * 4 + 3];
            const float* e = es + k4 * 16;
            a0 += e[0] * w0.x + e[1] * w0.y + e[2] * w0.z + e[3] * w0.w;
            a1 += e[4] * w1.x + e[5] * w1.y + e[6] * w1.z + e[7] * w1.w;
            a2 += e[8] * w2.x + e[9] * w2.y + e[10] * w2.z + e[11] * w2.w;
            a3 += e[12] * w3.x + e[13] * w3.y + e[14] * w3.z + e[15] * w3.w;
        }
        int np = (n & 255) * 4 + (n >> 8);
        g_projP[which][(size_t)v * GDIM + np] = (a0 + a1) + (a2 + a3) + b1[n] + b2[n];
    }
}

// ---------------- A-chunk loader (h splits, k=32) ----------------
__device__ __forceinline__ void load_chunk(uint32_t dst, const __half* __restrict__ A0,
                                           const __half* __restrict__ A1,
                                           int m0, int kb, int tid)
{
    const int row = tid >> 1;
    const int half = tid & 1;
    const uint32_t d0 = dst + (uint32_t)(row * 80 + half * 32);
    const size_t s0 = (size_t)(m0 + row) * HDIM + kb * 32 + half * 16;
    cpa16(d0,               A0 + s0);
    cpa16(d0 + 16,          A0 + s0 + 8);
    cpa16(d0 + A_PL_B,      A1 + s0);
    cpa16(d0 + A_PL_B + 16, A1 + s0 + 8);
}

// ---------------- persistent kernel ----------------
__global__ void __launch_bounds__(256, 1)
persist_kernel(const int* __restrict__ phon, const int* __restrict__ lens,
               const float* __restrict__ fcb, const int* __restrict__ sos,
               float* __restrict__ out)
{
    extern __shared__ char smem[];
    const uint32_t sb = smem_u32(smem);

    const int tid  = threadIdx.x;
    const int lane = tid & 31;
    const int wid  = tid >> 5;
    const int wm = wid & 1, wn = wid >> 1;
    const int bm = blockIdx.x >> 3, bn = blockIdx.x & 7;
    const int m0 = bm * MT;
    const int n0 = bn * NTP;
    const int j0g = bn * 32;

    unsigned sense = 0;
    const int sos0 = sos[0];

    if (tid < 32) ((float*)(smem + SM_BIAS))[tid] = fcb[bn * 32 + tid];
    if (tid < 128) ((int*)(smem + SM_TOK))[tid] = lens[m0 + tid];  // SLEN (enc phase)

    const int aRow = wm * 64 + (lane & 15);
    const int aCol = (lane >> 4) * 8;
    const int bRow = wn * 32 + ((lane & 16) >> 1) + (lane & 7);
    const int bColH = ((lane >> 3) & 1) * 8;
    const int myRow = wm * 64 + (lane >> 2) + (lane & 1) * 8;
    const int myUlB = wn * 8 + ((lane & 2) >> 1);
    const bool odd = (lane & 1);

    // resident W loader; also stages the fcW slice when entering decoder
    auto load_W = [&](int mode) {
        for (int f = tid; f < 8192; f += 256) {
            int p = f >> 12, rem = f & 4095;
            int row = rem >> 5, seg = rem & 31;
            cpa16(sb + SM_W + p * W_PLANE_B + row * W_ROW_B + seg * 16,
                  g_Ws[mode][p] + (size_t)(n0 + row) * HDIM + seg * 8);
        }
        if (mode) {
            for (int f = tid; f < 2048; f += 256) {
                int p = f >> 10, rem = f & 1023;
                int row = rem >> 5, seg = rem & 31;
                cpa16(sb + SM_FCW + p * FCW_PL_B + row * W_ROW_B + seg * 16,
                      g_fcWs[p] + (size_t)(bn * 32 + row) * HDIM + seg * 8);
            }
        }
        cpa_commit();
        cpa_wait<0>();
        __syncthreads();
    };
    load_W(0);

    float cpre[4][4];
#pragma unroll
    for (int i = 0; i < 4; i++)
#pragma unroll
        for (int j = 0; j < 4; j++) cpre[i][j] = 0.f;

    for (int t = 0; t < 2 * TPH; t++) {
        const int mode = (t >= TPH);
        if (t == TPH) {
            load_W(1);
#pragma unroll
            for (int i = 0; i < 4; i++)
#pragma unroll
                for (int j = 0; j < 4; j++) cpre[i][j] = 0.f;
        }
        const int inPar = t & 1, outPar = inPar ^ 1;
        const __half* A0 = (t == TPH) ? g_eL[0] : g_hs[inPar][0];
        const __half* A1 = (t == TPH) ? g_eL[1] : g_hs[inPar][1];

        // ---- token resolution ----
        int tokr[4];
        if (!mode) {
#pragma unroll
            for (int mt = 0; mt < 4; mt++)
                tokr[mt] = phon[(m0 + myRow + mt * 16) * TPH + t];
        } else if (t == TPH) {
#pragma unroll
            for (int mt = 0; mt < 4; mt++) tokr[mt] = sos0;
        } else {
            // reduce fc partials (8 slices) cooperatively
            float* PV = (float*)(smem + PV_OFF);
            int*   PI = (int*)(smem + PI_OFF);
#pragma unroll
            for (int i = 0; i < 4; i++) {
                int f = tid + i * 256;
                int bnp = f >> 7, lm = f & 127;
                PV[f] = g_pval[bnp][m0 + lm];
                PI[f] = g_pidx[bnp][m0 + lm];
            }
            __syncthreads();
            int* STOK = (int*)(smem + SM_TOK);
            if (tid < 128) {
                float bv = PV[tid];
                int   bi = PI[tid];
#pragma unroll
                for (int b = 1; b < 8; b++) {
                    float ov = PV[b * 128 + tid];
                    int   oi = PI[b * 128 + tid];
                    if (ov > bv || (ov == bv && oi < bi)) { bv = ov; bi = oi; }
                }
                STOK[tid] = bi;
            }
            __syncthreads();
#pragma unroll
            for (int mt = 0; mt < 4; mt++)
                tokr[mt] = STOK[myRow + mt * 16];
        }

        float acc[4][4][4];
#pragma unroll
        for (int i = 0; i < 4; i++)
#pragma unroll
            for (int j = 0; j < 4; j++)
#pragma unroll
                for (int q = 0; q < 4; q++) acc[i][j][q] = 0.f;

        load_chunk(sb + SM_STG, A0, A1, m0, 0, tid); cpa_commit();
        load_chunk(sb + SM_STG + A_CH_B, A0, A1, m0, 1, tid); cpa_commit();

        for (int kb = 0; kb < 8; kb++) {
            if (kb < 7) cpa_wait<1>(); else cpa_wait<0>();
            __syncthreads();
            if (kb < 6) {
                load_chunk(sb + SM_STG + ((kb + 2) % 3) * A_CH_B, A0, A1, m0, kb + 2, tid);
                cpa_commit();
            }
            const uint32_t bA = sb + SM_STG + (kb % 3) * A_CH_B;
#pragma unroll
            for (int k16 = 0; k16 < 2; k16++) {
                const uint32_t aOff = (uint32_t)(k16 * 16 + aCol) * 2;
                const uint32_t kW = (uint32_t)(kb * 32 + k16 * 16 + bColH) * 2;
                uint32_t ah[4][4], al[4][4], bh[2][4], bl[2][4];
#pragma unroll
                for (int mt = 0; mt < 4; mt++) {
                    ldsm4(ah[mt], bA + (uint32_t)(aRow + mt * 16) * 80 + aOff);
                    ldsm4(al[mt], bA + A_PL_B + (uint32_t)(aRow + mt * 16) * 80 + aOff);
                }
#pragma unroll
                for (int bg = 0; bg < 2; bg++) {
                    ldsm4(bh[bg], sb + SM_W + (uint32_t)(bRow + bg * 16) * W_ROW_B + kW);
                    ldsm4(bl[bg], sb + SM_W + W_PLANE_B
                                   + (uint32_t)(bRow + bg * 16) * W_ROW_B + kW);
                }
#pragma unroll
                for (int mt = 0; mt < 4; mt++)
#pragma unroll
                    for (int nt = 0; nt < 4; nt++) {
                        const int g = nt >> 1, s = (nt & 1) * 2;
                        mma16816(acc[mt][nt], ah[mt], bh[g][s], bh[g][s + 1]);
                    }
#pragma unroll
                for (int mt = 0; mt < 4; mt++)
#pragma unroll
                    for (int nt = 0; nt < 4; nt++) {
                        const int g = nt >> 1, s = (nt & 1) * 2;
                        mma16816(acc[mt][nt], ah[mt], bl[g][s], bl[g][s + 1]);
                    }
#pragma unroll
                for (int mt = 0; mt < 4; mt++)
#pragma unroll
                    for (int nt = 0; nt < 4; nt++) {
                        const int g = nt >> 1, s = (nt & 1) * 2;
                        mma16816(acc[mt][nt], al[mt], bh[g][s], bh[g][s + 1]);
                    }
            }
            __syncthreads();
        }

        // ---- epilogue ----
        __half* SHI = (__half*)(smem + SHI_OFF);
        __half* SLO = (__half*)(smem + SLO_OFF);
        const float* projT = g_projP[mode];
#pragma unroll
        for (int mt = 0; mt < 4; mt++) {
#pragma unroll
            for (int nt = 0; nt < 4; nt++) {
                const int ul = myUlB + nt * 2;
                const float4 p = *(const float4*)&projT[(size_t)tokr[mt] * GDIM
                                                        + n0 + ul * 4];
                float c0 = acc[mt][nt][0], c1 = acc[mt][nt][1];
                float c2 = acc[mt][nt][2], c3 = acc[mt][nt][3];
                float sA = odd ? c0 : c2;
                float sB = odd ? c1 : c3;
                float rA = __shfl_xor_sync(0xffffffffu, sA, 1);
                float rB = __shfl_xor_sync(0xffffffffu, sB, 1);
                float gi = odd ? rA : c0;
                float gf = odd ? rB : c1;
                float gg = odd ? c2 : rA;
                float go = odd ? c3 : rB;
                float iv = fast_sigmoid(gi + p.x);
                float fv = fast_sigmoid(gf + p.y);
                float gv = fast_tanh(gg + p.z);
                float ov = fast_sigmoid(go + p.w);
                float cn = fv * cpre[mt][nt] + iv * gv;
                cpre[mt][nt] = cn;
                float hv = ov * fast_tanh(cn);
                __half hi = __float2half_rn(hv);
                __half lo = __float2half_rn(hv - __half2float(hi));
                const int lr = myRow + mt * 16;
                SHI[lr * 34 + ul] = hi;
                SLO[lr * 34 + ul] = lo;
            }
        }
        __syncthreads();

        __half* oHi = g_hs[outPar][0];
        __half* oLo = g_hs[outPar][1];
        const int* SLEN = (const int*)(smem + SM_TOK);
#pragma unroll
        for (int i = 0; i < 16; i++) {
            int f = tid + i * 256;
            int lm = f >> 5, jl = f & 31;
            size_t gidx = (size_t)(m0 + lm) * HDIM + j0g + jl;
            __half hi = SHI[lm * 34 + jl];
            __half lo = SLO[lm * 34 + jl];
            oHi[gidx] = hi;
            oLo[gidx] = lo;
            if (!mode && t == SLEN[lm] - 1) {
                g_eL[0][gidx] = hi;
                g_eL[1][gidx] = lo;
            }
        }
        grid_sync(sense);

        // ================= fc: V-sliced, resident fcW =================
        if (mode) {
            const __half* hH = g_hs[outPar][0];
            const __half* hL = g_hs[outPar][1];
            const int wm2 = wid & 1, wn2 = wid >> 1;
            const int aRowF = wm2 * 64 + (lane & 15);
            const int fbRow = wn2 * 8 + (lane & 7);
            const int fbColH = ((lane >> 3) & 1) * 8;

            float accF[4][4];
#pragma unroll
            for (int i = 0; i < 4; i++)
#pragma unroll
                for (int j = 0; j < 4; j++) accF[i][j] = 0.f;

            load_chunk(sb + SM_STG, hH, hL, m0, 0, tid); cpa_commit();
            load_chunk(sb + SM_STG + A_CH_B, hH, hL, m0, 1, tid); cpa_commit();

            for (int kb = 0; kb < 8; kb++) {
                if (kb < 7) cpa_wait<1>(); else cpa_wait<0>();
                __syncthreads();
                if (kb < 6) {
                    load_chunk(sb + SM_STG + ((kb + 2) % 3) * A_CH_B, hH, hL, m0, kb + 2, tid);
                    cpa_commit();
                }
                const uint32_t bA = sb + SM_STG + (kb % 3) * A_CH_B;
#pragma unroll
                for (int k16 = 0; k16 < 2; k16++) {
                    const uint32_t aOff = (uint32_t)(k16 * 16 + aCol) * 2;
                    const uint32_t kF = (uint32_t)(kb * 32 + k16 * 16 + fbColH) * 2;
                    uint32_t fa_h[4][4], fa_l[4][4], fb_h[2], fb_l[2];
#pragma unroll
                    for (int mt = 0; mt < 4; mt++) {
                        ldsm4(fa_h[mt], bA + (uint32_t)(aRowF + mt * 16) * 80 + aOff);
                        ldsm4(fa_l[mt], bA + A_PL_B + (uint32_t)(aRowF + mt * 16) * 80 + aOff);
                    }
                    ldsm2(fb_h, sb + SM_FCW + (uint32_t)fbRow * W_ROW_B + kF);
                    ldsm2(fb_l, sb + SM_FCW + FCW_PL_B + (uint32_t)fbRow * W_ROW_B + kF);
#pragma unroll
                    for (int mt = 0; mt < 4; mt++) {
                        mma16816(accF[mt], fa_h[mt], fb_h[0], fb_h[1]);
                        mma16816(accF[mt], fa_h[mt], fb_l[0], fb_l[1]);
                        mma16816(accF[mt], fa_l[mt], fb_h[0], fb_h[1]);
                    }
                }
                __syncthreads();
            }

            // stage scores: rows 128, cols 8 per warp-n-group (total 32)
            float* SSC = (float*)(smem + SSC_OFF);
#pragma unroll
            for (int mt = 0; mt < 4; mt++) {
                int r = wm2 * 64 + mt * 16 + (lane >> 2);
                int c = wn2 * 8 + (lane & 3) * 2;
                SSC[r * 33 + c]       = accF[mt][0];
                SSC[r * 33 + c + 1]   = accF[mt][1];
                SSC[(r + 8) * 33 + c]     = accF[mt][2];
                SSC[(r + 8) * 33 + c + 1] = accF[mt][3];
            }
            __syncthreads();

            // bias + out + per-slice argmax; each warp handles 16 rows
            const float* SBIA = (const float*)(smem + SM_BIAS);
            const float myb = SBIA[lane];
#pragma unroll
            for (int rr = 0; rr < 16; rr++) {
                const int r = wid * 16 + rr;
                const int m = m0 + r;
                float s = SSC[r * 33 + lane] + myb;
                out[(size_t)m * (TPH * VOC) + (size_t)(t - TPH) * VOC + bn * 32 + lane] = s;
                float bv = s;
                int   bi = lane;
#pragma unroll
                for (int off = 16; off > 0; off >>= 1) {
                    float ov = __shfl_xor_sync(0xffffffffu, bv, off);
                    int   oi = __shfl_xor_sync(0xffffffffu, bi, off);
                    if (ov > bv || (ov == bv && oi < bi)) { bv = ov; bi = oi; }
                }
                if (lane == 0) {
                    g_pval[bn][m] = bv;
                    g_pidx[bn][m] = bn * 32 + bi;
                }
            }
            grid_sync(sense);
        }
    }
}

// ---------------- launch ----------------
extern "C" void kernel_launch(void* const* d_in, const int* in_sizes, int n_in,
                              void* d_out, int out_size)
{
    const int*   phon   = (const int*)  d_in[0];
    const int*   plen   = (const int*)  d_in[1];
    const float* emb    = (const float*)d_in[2];
    const float* encWih = (const float*)d_in[3];
    const float* encWhh = (const float*)d_in[4];
    const float* encBih = (const float*)d_in[5];
    const float* encBhh = (const float*)d_in[6];
    const float* decWih = (const float*)d_in[7];
    const float* decWhh = (const float*)d_in[8];
    const float* decBih = (const float*)d_in[9];
    const float* decBhh = (const float*)d_in[10];
    const float* fcW    = (const float*)d_in[11];
    const float* fcb    = (const float*)d_in[12];
    const int*   sos    = (const int*)  d_in[13];
    float* out = (float*)d_out;

    cudaFuncSetAttribute(persist_kernel,
                         cudaFuncAttributeMaxDynamicSharedMemorySize, SM_TOTAL);

    prep_kernel<<<6400, 256>>>(encWhh, decWhh, fcW, emb,
                               encWih, encBih, encBhh,
                               decWih, decBih, decBhh);

    persist_kernel<<<NCTA, 256, SM_TOTAL>>>(phon, plen, fcb, sos, out);
}